// round 11
// baseline (speedup 1.0000x reference)
#include <cuda_runtime.h>
#include <cuda_fp16.h>
#include <cstdint>

// ---------------------------------------------------------------------------
// Problem constants
// ---------------------------------------------------------------------------
#define M_DIM 16384   // B*S = 8*2048
#define N_DIM 4096    // OUT
#define K_DIM 4096    // IN
#define KE    4224    // extended K: 4096 + 8 adapters * 16 rank
#define BK    64
#define KT_CNT 66     // KE / 64
#define S_LEN 2048
#define R_RANK 16

// ---------------------------------------------------------------------------
// Device-global scratch
//  g_t  : t = x @ lora_a^T, fp32 [M, 16]  (accumulated via atomics)
//  g_xe : A image, fp16 + K-extended + FRAGMENT-PACKED (m16n8k16 layout)
//  g_we : B image likewise
// ---------------------------------------------------------------------------
__device__ __align__(16) float g_t[M_DIM * R_RANK];
__device__ __align__(1024) __half g_xe[(size_t)128 * KT_CNT * 8192];
__device__ __align__(1024) __half g_we[(size_t)32  * KT_CNT * 8192];

__device__ __forceinline__ uint32_t pack2(float lo, float hi) {
    __half2 h = __floats2half2_rn(lo, hi);
    return *(uint32_t*)&h;
}

// ---------------------------------------------------------------------------
// Kernel 0: zero g_t (required every call: graph replays reuse the global)
// ---------------------------------------------------------------------------
__global__ __launch_bounds__(256) void zero_t_kernel() {
    const uint32_t i = blockIdx.x * 256 + threadIdx.x;   // 65536 float4
    *(float4*)(g_t + i * 4) = make_float4(0.f, 0.f, 0.f, 0.f);
}

// ---------------------------------------------------------------------------
// Kernel 1: FUSED A-image build + partial-t accumulation.
// One block = one (mtile, ktile<64):
//   A) stage x 128x64 f32 -> smem (coalesced), stage la slice 16x64 -> smem
//   B) emit 1024 fragment-packed fp16 16B units (coalesced)
//   C) partial t: warp w owns rows w*16..w*16+15; lane = (row pair, r-half);
//      atomicAdd into g_t.
// NOTE: sx padded to 68 floats/row -> 272B stride, 16B-aligned rows (LDS.128
// legality). 66 would give 264B stride -> misaligned float4 on odd rows.
// ---------------------------------------------------------------------------
__global__ __launch_bounds__(256) void ext_a_fused_kernel(const float* __restrict__ x,
                                                          const float* __restrict__ la) {
    __shared__ __align__(16) float sx[128][68];
    __shared__ __align__(16) float sla[16][64];
    const int tid = threadIdx.x;
    const uint32_t ktile = blockIdx.x;      // < 64 (real K only)
    const uint32_t mtile = blockIdx.y;
    const uint32_t k0 = ktile * 64;
    const uint32_t adapter = mtile >> 4;    // uniform over 128-row tile

    // ---- A: stage x tile ----
#pragma unroll
    for (int i = 0; i < 8; i++) {
        const int idx = tid + i * 256;   // 2048 float4 slots
        const int row = idx >> 4;
        const int c4 = (idx & 15) * 4;
        const float4 v = *(const float4*)(x + (size_t)(mtile * 128 + row) * K_DIM + k0 + c4);
        *(float4*)&sx[row][c4] = v;
    }
    // stage la slice: 16 r x 64 k = 256 float4
    {
        const int r = tid >> 4;
        const int c4 = (tid & 15) * 4;
        const float4 v = *(const float4*)(la + ((size_t)adapter * R_RANK + r) * K_DIM + k0 + c4);
        *(float4*)&sla[r][c4] = v;
    }
    __syncthreads();

    // ---- B: fragment-pack to g_xe ----
    __half* dst = g_xe + (size_t)(mtile * KT_CNT + ktile) * 8192;
#pragma unroll
    for (int j = 0; j < 4; j++) {
        const uint32_t u = tid + j * 256;
        const uint32_t lane = u & 31;
        const uint32_t ks = (u >> 5) & 3;
        const uint32_t mt = (u >> 7) & 3;
        const uint32_t wm = (u >> 9) & 1;
        const uint32_t g = lane >> 2, tg = lane & 3;
        const uint32_t r0 = wm * 64 + mt * 16 + g;
        const uint32_t kk = ks * 16 + 2 * tg;

        const float2 p00 = *(const float2*)&sx[r0][kk];
        const float2 p10 = *(const float2*)&sx[r0 + 8][kk];
        const float2 p01 = *(const float2*)&sx[r0][kk + 8];
        const float2 p11 = *(const float2*)&sx[r0 + 8][kk + 8];
        uint4 v;
        v.x = pack2(p00.x, p00.y);
        v.y = pack2(p10.x, p10.y);
        v.z = pack2(p01.x, p01.y);
        v.w = pack2(p11.x, p11.y);
        *(uint4*)(dst + u * 8) = v;
    }

    // ---- C: partial t ----
    {
        const int w = tid >> 5;
        const int L = tid & 31;
        const int row = w * 16 + (L >> 1);        // local row 0..127
        const int rb = (L & 1) * 8;               // r-half
        float acc[8];
#pragma unroll
        for (int rr = 0; rr < 8; rr++) acc[rr] = 0.f;
#pragma unroll
        for (int kk = 0; kk < 16; kk++) {
            const float4 xv = *(const float4*)&sx[row][kk * 4];
#pragma unroll
            for (int rr = 0; rr < 8; rr++) {
                const float4 lv = *(const float4*)&sla[rb + rr][kk * 4];
                acc[rr] += xv.x * lv.x + xv.y * lv.y + xv.z * lv.z + xv.w * lv.w;
            }
        }
        float* tp = g_t + (size_t)(mtile * 128 + row) * R_RANK + rb;
#pragma unroll
        for (int rr = 0; rr < 8; rr++) atomicAdd(tp + rr, acc[rr]);
    }
}

// ---------------------------------------------------------------------------
// Kernel 2: A-image extension tail (ktiles 64,65) — needs FINAL g_t.
// ---------------------------------------------------------------------------
__global__ __launch_bounds__(256) void ext_a_tail_kernel() {
    const int tid = threadIdx.x;
    const uint32_t kt = 64 + blockIdx.x;    // 64 or 65
    const uint32_t mtile = blockIdx.y;

    __half* dst = g_xe + (size_t)(mtile * KT_CNT + kt) * 8192;
#pragma unroll
    for (int j = 0; j < 4; j++) {
        const uint32_t u = tid + j * 256;
        const uint32_t lane = u & 31;
        const uint32_t ks = (u >> 5) & 3;
        const uint32_t mt = (u >> 7) & 3;
        const uint32_t wm = (u >> 9) & 1;
        const uint32_t g = lane >> 2, tg = lane & 3;

        const uint32_t m0 = mtile * 128 + wm * 64 + mt * 16 + g;
        const uint32_t k0 = kt * 64 + ks * 16 + 2 * tg;
        const uint32_t e = k0 - K_DIM;      // pairs stay inside one 16-chunk
        const uint32_t a = e >> 4, r = e & 15;
        const uint32_t ad = m0 >> 11;

        uint4 v = make_uint4(0, 0, 0, 0);
        if (a == ad) {
            const float2 t00 = *(const float2*)(g_t + (size_t)m0 * R_RANK + r);
            const float2 t10 = *(const float2*)(g_t + (size_t)(m0 + 8) * R_RANK + r);
            const float2 t01 = *(const float2*)(g_t + (size_t)m0 * R_RANK + r + 8);
            const float2 t11 = *(const float2*)(g_t + (size_t)(m0 + 8) * R_RANK + r + 8);
            v.x = pack2(2.f * t00.x, 2.f * t00.y);
            v.y = pack2(2.f * t10.x, 2.f * t10.y);
            v.z = pack2(2.f * t01.x, 2.f * t01.y);
            v.w = pack2(2.f * t11.x, 2.f * t11.y);
        }
        *(uint4*)(dst + u * 8) = v;
    }
}

// ---------------------------------------------------------------------------
// Kernel 3: B image, SMEM-STAGED (coalesced W reads). One block per
// (ktile, ntile); extension ktiles take the direct (tiny) path.
// ---------------------------------------------------------------------------
__global__ __launch_bounds__(256) void ext_b_kernel(const float* __restrict__ W,
                                                    const float* __restrict__ lb) {
    __shared__ __align__(16) float sw[128][68];
    const int tid = threadIdx.x;
    const uint32_t ktile = blockIdx.x;   // 0..65
    const uint32_t ntile = blockIdx.y;   // 0..31
    const uint32_t k0b = ktile * 64;
    __half* dst = g_we + (size_t)(ntile * KT_CNT + ktile) * 8192;

    if (k0b < K_DIM) {
#pragma unroll
        for (int i = 0; i < 8; i++) {
            const int idx = tid + i * 256;
            const int row = idx >> 4;          // col index within 128
            const int c4 = (idx & 15) * 4;
            const float4 v =
                *(const float4*)(W + (size_t)(ntile * 128 + row) * K_DIM + k0b + c4);
            *(float4*)&sw[row][c4] = v;
        }
        __syncthreads();
#pragma unroll
        for (int j = 0; j < 4; j++) {
            const uint32_t u = tid + j * 256;
            const uint32_t lane = u & 31;
            const uint32_t ks = (u >> 5) & 3;
            const uint32_t ntp = (u >> 7) & 1;
            const uint32_t wn = (u >> 8) & 3;
            const uint32_t g = lane >> 2, tg = lane & 3;
            const uint32_t c0 = wn * 32 + ntp * 16 + g;    // local col, c0 and c0+8
            const uint32_t kk = ks * 16 + 2 * tg;

            const float2 p00 = *(const float2*)&sw[c0][kk];
            const float2 p01 = *(const float2*)&sw[c0][kk + 8];
            const float2 p10 = *(const float2*)&sw[c0 + 8][kk];
            const float2 p11 = *(const float2*)&sw[c0 + 8][kk + 8];
            uint4 v;
            v.x = pack2(p00.x, p00.y);
            v.y = pack2(p01.x, p01.y);
            v.z = pack2(p10.x, p10.y);
            v.w = pack2(p11.x, p11.y);
            *(uint4*)(dst + u * 8) = v;
        }
    } else {
        // extension ktiles (64,65): read lora_b directly (tiny, L2-resident)
#pragma unroll
        for (int j = 0; j < 4; j++) {
            const uint32_t u = tid + j * 256;
            const uint32_t lane = u & 31;
            const uint32_t ks = (u >> 5) & 3;
            const uint32_t ntp = (u >> 7) & 1;
            const uint32_t wn = (u >> 8) & 3;
            const uint32_t g = lane >> 2, tg = lane & 3;
            const uint32_t c0 = ntile * 128 + wn * 32 + ntp * 16 + g;
            const uint32_t k0 = k0b + ks * 16 + 2 * tg;
            const uint32_t e = k0 - K_DIM;
            const uint32_t a = e >> 4, r = e & 15;
            const float* p0 = lb + ((size_t)a * N_DIM + c0) * R_RANK;
            const float* p1 = lb + ((size_t)a * N_DIM + c0 + 8) * R_RANK;
            uint4 v;
            v.x = pack2(p0[r], p0[r + 1]);
            v.y = pack2(p0[r + 8], p0[r + 9]);
            v.z = pack2(p1[r], p1[r + 1]);
            v.w = pack2(p1[r + 8], p1[r + 9]);
            *(uint4*)(dst + u * 8) = v;
        }
    }
}

// ---------------------------------------------------------------------------
// Kernel 4: GEMM — R5 config (known-good): 128x128x64 tiles, fp16 m16n8k16,
// fragment-packed smem, 3-stage cp.async pipeline, 2 CTAs/SM.
// Per warp-ktile: 24 LDS.128 + 64 MMA.
// ---------------------------------------------------------------------------
#define STAGES 3
#define TILE_BYTES 16384
#define STAGE_BYTES (2 * TILE_BYTES)          // A + B = 32KB
#define SMEM_BYTES (STAGES * STAGE_BYTES)     // 98304

__device__ __forceinline__ void mma_f16(float* c, const uint32_t* a, const uint32_t* b) {
    asm volatile(
        "mma.sync.aligned.m16n8k16.row.col.f32.f16.f16.f32 "
        "{%0,%1,%2,%3}, {%4,%5,%6,%7}, {%8,%9}, {%0,%1,%2,%3};"
        : "+f"(c[0]), "+f"(c[1]), "+f"(c[2]), "+f"(c[3])
        : "r"(a[0]), "r"(a[1]), "r"(a[2]), "r"(a[3]), "r"(b[0]), "r"(b[1]));
}

__global__ __launch_bounds__(256, 2) void lora_gemm_kernel(float* __restrict__ out) {
    extern __shared__ char smem[];
    const int tid = threadIdx.x;
    const int lane = tid & 31;
    const int warp = tid >> 5;
    const int warp_m = warp >> 2;   // 0..1
    const int warp_n = warp & 3;    // 0..3
    const int g = lane >> 2;
    const int tg = lane & 3;
    const uint32_t mtile = blockIdx.y;
    const uint32_t ntile = blockIdx.x;

    float acc[4][4][4];
#pragma unroll
    for (int mt = 0; mt < 4; mt++)
#pragma unroll
        for (int nt = 0; nt < 4; nt++)
#pragma unroll
            for (int c = 0; c < 4; c++) acc[mt][nt][c] = 0.f;

    const char* gA = (const char*)g_xe + ((size_t)mtile * KT_CNT << 14);
    const char* gB = (const char*)g_we + ((size_t)ntile * KT_CNT << 14);

    auto load_tile = [&](int stage, int kt) {
        char* st = smem + stage * STAGE_BYTES;
        const char* sa = gA + ((size_t)kt << 14);
        const char* sb = gB + ((size_t)kt << 14);
#pragma unroll
        for (int i = 0; i < 4; i++) {
            const int off = (tid + i * 256) * 16;
            uint32_t dA = (uint32_t)__cvta_generic_to_shared(st + off);
            asm volatile("cp.async.cg.shared.global [%0], [%1], 16;" ::"r"(dA), "l"(sa + off));
            uint32_t dB = (uint32_t)__cvta_generic_to_shared(st + TILE_BYTES + off);
            asm volatile("cp.async.cg.shared.global [%0], [%1], 16;" ::"r"(dB), "l"(sb + off));
        }
    };

    auto compute_tile = [&](int stage) {
        const char* sA = smem + stage * STAGE_BYTES;
        const char* sB = sA + TILE_BYTES;
#pragma unroll
        for (int ks = 0; ks < 4; ks++) {
            uint4 af[4];
#pragma unroll
            for (int mt = 0; mt < 4; mt++)
                af[mt] = *(const uint4*)(sA + (((warp_m * 4 + mt) * 4 + ks) * 32 + lane) * 16);
            uint4 bv[2];
#pragma unroll
            for (int ntp = 0; ntp < 2; ntp++)
                bv[ntp] = *(const uint4*)(sB + (((warp_n * 2 + ntp) * 4 + ks) * 32 + lane) * 16);
            uint32_t bf[4][2];
#pragma unroll
            for (int ntp = 0; ntp < 2; ntp++) {
                bf[2 * ntp][0] = bv[ntp].x;
                bf[2 * ntp][1] = bv[ntp].y;
                bf[2 * ntp + 1][0] = bv[ntp].z;
                bf[2 * ntp + 1][1] = bv[ntp].w;
            }
#pragma unroll
            for (int mt = 0; mt < 4; mt++)
#pragma unroll
                for (int nt = 0; nt < 4; nt++)
                    mma_f16(acc[mt][nt], (const uint32_t*)&af[mt], bf[nt]);
        }
    };

#pragma unroll
    for (int s = 0; s < STAGES - 1; s++) {
        load_tile(s, s);
        asm volatile("cp.async.commit_group;");
    }
    for (int kt = 0; kt < KT_CNT; kt++) {
        asm volatile("cp.async.wait_group %0;" ::"n"(STAGES - 2));
        __syncthreads();
        const int nxt = kt + STAGES - 1;
        if (nxt < KT_CNT) load_tile(nxt % STAGES, nxt);
        asm volatile("cp.async.commit_group;");
        compute_tile(kt % STAGES);
    }

    // ---- pure-store epilogue (LoRA already folded into K) ----
#pragma unroll
    for (int mt = 0; mt < 4; mt++)
#pragma unroll
        for (int i = 0; i < 2; i++) {
            const size_t row = (size_t)mtile * 128 + warp_m * 64 + mt * 16 + g + i * 8;
#pragma unroll
            for (int nt = 0; nt < 4; nt++) {
                const uint32_t col = ntile * 128 + warp_n * 32 + nt * 8 + tg * 2;
                *(float2*)&out[row * N_DIM + col] =
                    make_float2(acc[mt][nt][i * 2 + 0], acc[mt][nt][i * 2 + 1]);
            }
        }
}

// ---------------------------------------------------------------------------
// Harness entry
// d_in[0]=data [8,2048,4096] f32, d_in[1]=W [4096,4096] f32,
// d_in[2]=lora_a [8,16,4096] f32, d_in[3]=lora_b [8,4096,16] f32
// ---------------------------------------------------------------------------
extern "C" void kernel_launch(void* const* d_in, const int* in_sizes, int n_in,
                              void* d_out, int out_size) {
    const float* x = (const float*)d_in[0];
    const float* W = (const float*)d_in[1];
    const float* la = (const float*)d_in[2];
    const float* lb = (const float*)d_in[3];
    float* out = (float*)d_out;

    cudaFuncSetAttribute(lora_gemm_kernel,
                         cudaFuncAttributeMaxDynamicSharedMemorySize, SMEM_BYTES);

    zero_t_kernel<<<256, 256>>>();
    {
        dim3 ga(64, M_DIM / 128);        // real-K tiles: fused pack + partial t
        ext_a_fused_kernel<<<ga, 256>>>(x, la);
    }
    {
        dim3 gt(2, M_DIM / 128);         // extension ktiles (needs final g_t)
        ext_a_tail_kernel<<<gt, 256>>>();
    }
    {
        dim3 gb(KT_CNT, N_DIM / 128);    // staged B image
        ext_b_kernel<<<gb, 256>>>(W, lb);
    }
    dim3 grid(N_DIM / 128, M_DIM / 128); // (32, 128)
    lora_gemm_kernel<<<grid, 256, SMEM_BYTES>>>(out);
}